// round 3
// baseline (speedup 1.0000x reference)
#include <cuda_runtime.h>
#include <cstdint>

#define NBATCH 4
#define LRES   256
#define NATOM  14
#define FEAT   128
#define MPAIR  196      // NATOM*NATOM
#define MAXAA  22
#define NAPAIR 484      // MAXAA*MAXAA
#define NREL   65

typedef unsigned long long ull;

// ---------------- scratch (static __device__ — no allocations allowed) ----------------
__device__ float g_softc[NAPAIR * MPAIR];          // softplus(distcoef_embed)
__device__ float g_preA [NAPAIR * FEAT];           // aa_pair_embed @ out_w1[0:128]
__device__ float g_preR [NREL   * FEAT];           // relpos_embed  @ out_w1[128:256]
__device__ float g_dihed[NBATCH * LRES * LRES * 2];// (phi, psi) per pair

// ---------------- packed f32x2 helpers ----------------
__device__ __forceinline__ ull pack2(float lo, float hi) {
    ull r; asm("mov.b64 %0, {%1, %2};" : "=l"(r) : "f"(lo), "f"(hi)); return r;
}
__device__ __forceinline__ void fma2(ull& d, ull a, ull b) {
    asm("fma.rn.f32x2 %0, %1, %2, %0;" : "+l"(d) : "l"(a), "l"(b));
}
__device__ __forceinline__ float2 unpack2(ull v) {
    float2 r; asm("mov.b64 {%0, %1}, %2;" : "=f"(r.x), "=f"(r.y) : "l"(v)); return r;
}

// ---------------- small precompute kernels ----------------
__global__ void softc_kernel(const float* __restrict__ distcoef) {
    int idx = blockIdx.x * 256 + threadIdx.x;
    if (idx < NAPAIR * MPAIR) {
        float x = distcoef[idx];
        g_softc[idx] = (x > 20.f) ? x : log1pf(expf(x));
    }
}

__global__ void pretab_kernel(const float* __restrict__ aa_pair_embed,
                              const float* __restrict__ relpos_embed,
                              const float* __restrict__ ow1) {
    __shared__ float e[FEAT];
    int b = blockIdx.x, f = threadIdx.x;
    if (b < NAPAIR) {
        e[f] = aa_pair_embed[b * FEAT + f];
        __syncthreads();
        float acc = 0.f;
        #pragma unroll 8
        for (int k = 0; k < FEAT; k++) acc += e[k] * ow1[k * FEAT + f];
        g_preA[b * FEAT + f] = acc;
    } else {
        int r = b - NAPAIR;
        e[f] = relpos_embed[r * FEAT + f];
        __syncthreads();
        float acc = 0.f;
        #pragma unroll 8
        for (int k = 0; k < FEAT; k++) acc += e[k] * ow1[(FEAT + k) * FEAT + f];
        g_preR[r * FEAT + f] = acc;
    }
}

__device__ __forceinline__ float3 f3sub(float3 a, float3 b) { return make_float3(a.x-b.x, a.y-b.y, a.z-b.z); }
__device__ __forceinline__ float3 f3cross(float3 a, float3 b) {
    return make_float3(a.y*b.z - a.z*b.y, a.z*b.x - a.x*b.z, a.x*b.y - a.y*b.x);
}
__device__ __forceinline__ float f3dot(float3 a, float3 b) { return a.x*b.x + a.y*b.y + a.z*b.z; }

__device__ __forceinline__ float dihedral_f(float3 p0, float3 p1, float3 p2, float3 p3) {
    float3 v0 = f3sub(p2, p1), v1 = f3sub(p0, p1), v2 = f3sub(p3, p2);
    float3 u1 = f3cross(v0, v1), u2 = f3cross(v0, v2);
    float nn = f3dot(u1, u1) * f3dot(u2, u2);
    if (!(nn > 0.f)) return 0.f;                      // matches nan_to_num path
    float cosv = f3dot(u1, u2) * rsqrtf(nn);
    cosv = fminf(fmaxf(cosv, -0.999999f), 0.999999f);
    float sd = f3dot(f3cross(v1, v2), v0);
    float sgn = (sd > 0.f) ? 1.f : ((sd < 0.f) ? -1.f : 0.f);
    float d = sgn * acosf(cosv);
    return isfinite(d) ? d : 0.f;
}

__global__ void dihed_kernel(const float* __restrict__ pos) {
    int idx = blockIdx.x * 256 + threadIdx.x;        // NB*L*L threads exactly
    int n = idx >> 16, i = (idx >> 8) & 255, j = idx & 255;
    const float* pi = pos + (size_t)(n * LRES + i) * NATOM * 3;
    const float* pj = pos + (size_t)(n * LRES + j) * NATOM * 3;
    float3 Ni  = make_float3(pi[0], pi[1], pi[2]);
    float3 CAi = make_float3(pi[3], pi[4], pi[5]);
    float3 Ci  = make_float3(pi[6], pi[7], pi[8]);
    float3 Nj  = make_float3(pj[0], pj[1], pj[2]);
    float3 CAj = make_float3(pj[3], pj[4], pj[5]);
    float3 Cj  = make_float3(pj[6], pj[7], pj[8]);
    float phi = dihedral_f(Ci, Nj, CAj, Cj);         // ir_phi[i,j]
    float psi = dihedral_f(Ni, CAi, Ci, Nj);         // ir_psi[i,j]
    g_dihed[(size_t)idx * 2 + 0] = phi;
    g_dihed[(size_t)idx * 2 + 1] = psi;
}

// ---------------- fused main kernel ----------------
struct Smem {
    float buf0[64 * MPAIR];   // G (stride 196) / reused as [64][128]
    float buf1[64 * FEAT];
    float w[16 * FEAT];       // weight tile
    float wdh[26 * FEAT];     // dihedral weight block (out_w1 rows 384..409)
    float posI[8 * NATOM * 3];
    float posJ[8 * NATOM * 3];
    float maskI[8 * NATOM];
    float maskJ[8 * NATOM];
    float dcode[64 * 26];
    float b1[FEAT]; float b2[FEAT]; float b3[FEAT]; float b4[FEAT]; float b5[FEAT];
    float sc[64]; float mp[64];
    int aap[64]; int rel[64];
    int aaI[8]; int aaJ[8]; int resI[8]; int resJ[8]; int chI[8]; int chJ[8];
};

// 64x128 output tile accumulate: out[p][f] += sum_k act[p][k] * W[k][f]
// acc: 16 packed-f32x2 registers, pairs (2pp, 2pp+1) per 64-bit reg. fx=lane, py=warp.
template<int K, int KT, int STRIDE>
__device__ __forceinline__ void gemm_acc(const float* __restrict__ Wg,
                                         const float* __restrict__ sAct,
                                         float* __restrict__ sW,
                                         ull acc[16], int tid, int fx, int py) {
    #pragma unroll 1
    for (int k0 = 0; k0 < K; k0 += KT) {
        __syncthreads();
        for (int idx = tid; idx < KT * 32; idx += 256) {
            int kk = idx >> 5;
            int ff = (idx & 31) << 2;
            *(float4*)&sW[kk * FEAT + ff] = *(const float4*)&Wg[(k0 + kk) * FEAT + ff];
        }
        __syncthreads();
        const float* abase = sAct + py * 8 * STRIDE + k0;
        #pragma unroll
        for (int kk = 0; kk < KT; kk++) {
            float4 w = *(const float4*)&sW[kk * FEAT + (fx << 2)];
            ull wv0 = pack2(w.x, w.x), wv1 = pack2(w.y, w.y);
            ull wv2 = pack2(w.z, w.z), wv3 = pack2(w.w, w.w);
            #pragma unroll
            for (int pp = 0; pp < 4; pp++) {
                float a0 = abase[(2 * pp)     * STRIDE + kk];
                float a1 = abase[(2 * pp + 1) * STRIDE + kk];
                ull av = pack2(a0, a1);
                fma2(acc[pp * 4 + 0], av, wv0);
                fma2(acc[pp * 4 + 1], av, wv1);
                fma2(acc[pp * 4 + 2], av, wv2);
                fma2(acc[pp * 4 + 3], av, wv3);
            }
        }
    }
}

__device__ __forceinline__ void store_smem(ull acc[16], const float* bias,
                                           float* dst, int fx, int py) {
    int f = fx << 2;
    #pragma unroll
    for (int pp = 0; pp < 4; pp++) {
        int p0 = py * 8 + 2 * pp;
        #pragma unroll
        for (int fi = 0; fi < 4; fi++) {
            float2 v = unpack2(acc[pp * 4 + fi]);
            float b = bias[f + fi];
            dst[p0 * FEAT + f + fi]       = fmaxf(v.x + b, 0.f);
            dst[(p0 + 1) * FEAT + f + fi] = fmaxf(v.y + b, 0.f);
        }
    }
}

__global__ void __launch_bounds__(256, 1)
fused_kernel(const int* __restrict__ aa, const int* __restrict__ res_nb,
             const int* __restrict__ chain_nb, const float* __restrict__ pos,
             const float* __restrict__ mask,
             const float* __restrict__ dw1, const float* __restrict__ db1,
             const float* __restrict__ dw2, const float* __restrict__ db2,
             const float* __restrict__ ow1, const float* __restrict__ ob1,
             const float* __restrict__ ow2, const float* __restrict__ ob2,
             const float* __restrict__ ow3, const float* __restrict__ ob3,
             float* __restrict__ outp) {
    extern __shared__ char smem_raw[];
    Smem& s = *reinterpret_cast<Smem*>(smem_raw);
    const int tid = threadIdx.x;
    const int fx = tid & 31, py = tid >> 5;
    const int bid = blockIdx.x;
    const int n  = bid >> 10;
    const int i0 = ((bid >> 5) & 31) * 8;
    const int j0 = (bid & 31) * 8;

    // ---- phase 0: cooperative loads ----
    {
        const float* pbI = pos + (size_t)(n * LRES + i0) * NATOM * 3;
        const float* pbJ = pos + (size_t)(n * LRES + j0) * NATOM * 3;
        for (int idx = tid; idx < 8 * NATOM * 3; idx += 256) { s.posI[idx] = pbI[idx]; s.posJ[idx] = pbJ[idx]; }
        const float* mbI = mask + (size_t)(n * LRES + i0) * NATOM;
        const float* mbJ = mask + (size_t)(n * LRES + j0) * NATOM;
        if (tid < 8 * NATOM) { s.maskI[tid] = mbI[tid]; s.maskJ[tid] = mbJ[tid]; }
        if (tid < 8) {
            s.aaI[tid]  = aa[n * LRES + i0 + tid];  s.aaJ[tid]  = aa[n * LRES + j0 + tid];
            s.resI[tid] = res_nb[n * LRES + i0 + tid]; s.resJ[tid] = res_nb[n * LRES + j0 + tid];
            s.chI[tid]  = chain_nb[n * LRES + i0 + tid]; s.chJ[tid] = chain_nb[n * LRES + j0 + tid];
        }
        if (tid < 128) {
            s.b1[tid] = db1[tid]; s.b2[tid] = db2[tid]; s.b3[tid] = ob1[tid];
            s.b4[tid] = ob2[tid]; s.b5[tid] = ob3[tid];
        }
        for (int idx = tid; idx < 26 * FEAT; idx += 256) s.wdh[idx] = ow1[384 * FEAT + idx];
    }
    __syncthreads();

    // ---- phase 0b: per-pair meta + dihedral angular codes ----
    if (tid < 64) {
        int ii = tid >> 3, jj = tid & 7;
        s.aap[tid] = s.aaI[ii] * MAXAA + s.aaJ[jj];
        int r = s.resI[ii] - s.resJ[jj];
        s.rel[tid] = min(max(r, -32), 32) + 32;
        s.sc[tid] = (s.chI[ii] == s.chJ[jj]) ? 1.f : 0.f;
        s.mp[tid] = s.maskI[ii * NATOM + 1] * s.maskJ[jj * NATOM + 1];   // CA masks
        const float* dh = &g_dihed[((size_t)(n * LRES + i0 + ii) * LRES + (j0 + jj)) * 2];
        float phi = dh[0], psi = dh[1];
        float* c = &s.dcode[tid * 26];
        const float FRQ[6] = {1.f, 2.f, 3.f, 1.f, 0.5f, 1.f / 3.f};
        c[0] = phi; c[13] = psi;
        #pragma unroll
        for (int t = 0; t < 6; t++) {
            float sv, cv;
            sincosf(phi * FRQ[t], &sv, &cv); c[1 + t]  = sv; c[7 + t]  = cv;
            sincosf(psi * FRQ[t], &sv, &cv); c[14 + t] = sv; c[20 + t] = cv;
        }
    }
    __syncthreads();

    // ---- phase 1: masked gaussian distance features G[64][196] ----
    for (int idx = tid; idx < 64 * MPAIR; idx += 256) {
        int p = idx / MPAIR;
        int m = idx - p * MPAIR;
        int a = m / NATOM;
        int b = m - a * NATOM;
        int ii = p >> 3, jj = p & 7;
        float dx = s.posI[ii * 42 + a * 3 + 0] - s.posJ[jj * 42 + b * 3 + 0];
        float dy = s.posI[ii * 42 + a * 3 + 1] - s.posJ[jj * 42 + b * 3 + 1];
        float dz = s.posI[ii * 42 + a * 3 + 2] - s.posJ[jj * 42 + b * 3 + 2];
        float ss = dx * dx + dy * dy + dz * dz;        // (10*d)^2
        float cc = g_softc[s.aap[p] * MPAIR + m];
        float g = __expf(-cc * ss * 0.01f) * (s.maskI[ii * NATOM + a] * s.maskJ[jj * NATOM + b]);
        s.buf0[p * MPAIR + m] = g;
    }
    // gemm's leading __syncthreads covers buf0 visibility

    ull acc[16];

    // ---- stage 1: h1 = relu(G @ dist_w1 + b1) ----
    #pragma unroll
    for (int q = 0; q < 16; q++) acc[q] = 0ull;
    gemm_acc<MPAIR, 14, MPAIR>(dw1, s.buf0, s.w, acc, tid, fx, py);
    store_smem(acc, s.b1, s.buf1, fx, py);

    // ---- stage 2: fd = relu(h1 @ dist_w2 + b2) ----
    #pragma unroll
    for (int q = 0; q < 16; q++) acc[q] = 0ull;
    gemm_acc<FEAT, 16, FEAT>(dw2, s.buf1, s.w, acc, tid, fx, py);
    store_smem(acc, s.b2, s.buf0, fx, py);

    // ---- stage 3: h = relu(preA + sc*preR + dihed@Wdh + fd@Wdist + out_b1) ----
    {
        int f = fx << 2;
        #pragma unroll
        for (int pp = 0; pp < 4; pp++) {
            int p0 = py * 8 + 2 * pp, p1 = p0 + 1;
            float4 A0 = *(const float4*)&g_preA[s.aap[p0] * FEAT + f];
            float4 A1 = *(const float4*)&g_preA[s.aap[p1] * FEAT + f];
            float4 R0 = *(const float4*)&g_preR[s.rel[p0] * FEAT + f];
            float4 R1 = *(const float4*)&g_preR[s.rel[p1] * FEAT + f];
            float sc0 = s.sc[p0], sc1 = s.sc[p1];
            acc[pp * 4 + 0] = pack2(A0.x + sc0 * R0.x, A1.x + sc1 * R1.x);
            acc[pp * 4 + 1] = pack2(A0.y + sc0 * R0.y, A1.y + sc1 * R1.y);
            acc[pp * 4 + 2] = pack2(A0.z + sc0 * R0.z, A1.z + sc1 * R1.z);
            acc[pp * 4 + 3] = pack2(A0.w + sc0 * R0.w, A1.w + sc1 * R1.w);
        }
        #pragma unroll
        for (int t = 0; t < 26; t++) {
            float4 w = *(const float4*)&s.wdh[t * FEAT + f];
            ull wv0 = pack2(w.x, w.x), wv1 = pack2(w.y, w.y);
            ull wv2 = pack2(w.z, w.z), wv3 = pack2(w.w, w.w);
            #pragma unroll
            for (int pp = 0; pp < 4; pp++) {
                int p0 = py * 8 + 2 * pp;
                ull av = pack2(s.dcode[p0 * 26 + t], s.dcode[(p0 + 1) * 26 + t]);
                fma2(acc[pp * 4 + 0], av, wv0);
                fma2(acc[pp * 4 + 1], av, wv1);
                fma2(acc[pp * 4 + 2], av, wv2);
                fma2(acc[pp * 4 + 3], av, wv3);
            }
        }
    }
    gemm_acc<FEAT, 16, FEAT>(ow1 + 256 * FEAT, s.buf0, s.w, acc, tid, fx, py);
    store_smem(acc, s.b3, s.buf1, fx, py);

    // ---- stage 4: h = relu(h @ out_w2 + b2) ----
    #pragma unroll
    for (int q = 0; q < 16; q++) acc[q] = 0ull;
    gemm_acc<FEAT, 16, FEAT>(ow2, s.buf1, s.w, acc, tid, fx, py);
    store_smem(acc, s.b4, s.buf0, fx, py);

    // ---- stage 5: out = (h @ out_w3 + b3) * mask_pair -> global ----
    #pragma unroll
    for (int q = 0; q < 16; q++) acc[q] = 0ull;
    gemm_acc<FEAT, 16, FEAT>(ow3, s.buf0, s.w, acc, tid, fx, py);
    {
        int f = fx << 2;
        #pragma unroll
        for (int pp = 0; pp < 4; pp++) {
            int p0 = py * 8 + 2 * pp, p1 = p0 + 1;
            float mp0 = s.mp[p0], mp1 = s.mp[p1];
            float2 v0 = unpack2(acc[pp * 4 + 0]);
            float2 v1 = unpack2(acc[pp * 4 + 1]);
            float2 v2 = unpack2(acc[pp * 4 + 2]);
            float2 v3 = unpack2(acc[pp * 4 + 3]);
            float bb0 = s.b5[f], bb1 = s.b5[f + 1], bb2 = s.b5[f + 2], bb3 = s.b5[f + 3];
            float4 o0 = make_float4((v0.x + bb0) * mp0, (v1.x + bb1) * mp0,
                                    (v2.x + bb2) * mp0, (v3.x + bb3) * mp0);
            float4 o1 = make_float4((v0.y + bb0) * mp1, (v1.y + bb1) * mp1,
                                    (v2.y + bb2) * mp1, (v3.y + bb3) * mp1);
            int gi = i0 + py;
            int gj0 = j0 + 2 * pp, gj1 = gj0 + 1;
            *(float4*)&outp[(((size_t)n * LRES + gi) * LRES + gj0) * FEAT + f] = o0;
            *(float4*)&outp[(((size_t)n * LRES + gi) * LRES + gj1) * FEAT + f] = o1;
        }
    }
}

// ---------------- launch ----------------
extern "C" void kernel_launch(void* const* d_in, const int* in_sizes, int n_in,
                              void* d_out, int out_size) {
    const int*   aa        = (const int*)  d_in[0];
    const int*   res_nb    = (const int*)  d_in[1];
    const int*   chain_nb  = (const int*)  d_in[2];
    const float* pos       = (const float*)d_in[3];
    const float* mask      = (const float*)d_in[4];
    const float* aap_embed = (const float*)d_in[5];
    const float* rel_embed = (const float*)d_in[6];
    const float* distcoef  = (const float*)d_in[7];
    const float* dw1 = (const float*)d_in[8];
    const float* db1 = (const float*)d_in[9];
    const float* dw2 = (const float*)d_in[10];
    const float* db2 = (const float*)d_in[11];
    const float* ow1 = (const float*)d_in[12];
    const float* ob1 = (const float*)d_in[13];
    const float* ow2 = (const float*)d_in[14];
    const float* ob2 = (const float*)d_in[15];
    const float* ow3 = (const float*)d_in[16];
    const float* ob3 = (const float*)d_in[17];
    float* outp = (float*)d_out;

    cudaFuncSetAttribute(fused_kernel, cudaFuncAttributeMaxDynamicSharedMemorySize,
                         (int)sizeof(Smem));

    softc_kernel<<<(NAPAIR * MPAIR + 255) / 256, 256>>>(distcoef);
    pretab_kernel<<<NAPAIR + NREL, 128>>>(aap_embed, rel_embed, ow1);
    dihed_kernel<<<(NBATCH * LRES * LRES) / 256, 256>>>(pos);
    fused_kernel<<<NBATCH * 32 * 32, 256, sizeof(Smem)>>>(
        aa, res_nb, chain_nb, pos, mask,
        dw1, db1, dw2, db2, ow1, ob1, ow2, ob2, ow3, ob3, outp);
}

// round 4
// speedup vs baseline: 1.0756x; 1.0756x over previous
#include <cuda_runtime.h>
#include <cstdint>

#define NBATCH 4
#define LRES   256
#define NATOM  14
#define FEAT   128
#define MPAIR  196      // NATOM*NATOM
#define MAXAA  22
#define NAPAIR 484      // MAXAA*MAXAA
#define NREL   65

typedef unsigned long long ull;

// ---------------- scratch (static __device__ — no allocations allowed) ----------------
__device__ float g_softc[NAPAIR * MPAIR];          // softplus(distcoef_embed)
__device__ float g_preA [NAPAIR * FEAT];           // aa_pair_embed @ out_w1[0:128]
__device__ float g_preR [NREL   * FEAT];           // relpos_embed  @ out_w1[128:256]
__device__ float g_dihed[NBATCH * LRES * LRES * 2];// (phi, psi) per pair

// ---------------- packed f32x2 helpers ----------------
__device__ __forceinline__ ull pack2(float lo, float hi) {
    ull r; asm("mov.b64 %0, {%1, %2};" : "=l"(r) : "f"(lo), "f"(hi)); return r;
}
__device__ __forceinline__ void fma2(ull& d, ull a, ull b) {
    asm("fma.rn.f32x2 %0, %1, %2, %0;" : "+l"(d) : "l"(a), "l"(b));
}
__device__ __forceinline__ float2 unpack2(ull v) {
    float2 r; asm("mov.b64 {%0, %1}, %2;" : "=f"(r.x), "=f"(r.y) : "l"(v)); return r;
}

// ---------------- small precompute kernels ----------------
__global__ void softc_kernel(const float* __restrict__ distcoef) {
    int idx = blockIdx.x * 256 + threadIdx.x;
    if (idx < NAPAIR * MPAIR) {
        float x = distcoef[idx];
        g_softc[idx] = (x > 20.f) ? x : log1pf(expf(x));
    }
}

__global__ void pretab_kernel(const float* __restrict__ aa_pair_embed,
                              const float* __restrict__ relpos_embed,
                              const float* __restrict__ ow1) {
    __shared__ float e[FEAT];
    int b = blockIdx.x, f = threadIdx.x;
    if (b < NAPAIR) {
        e[f] = aa_pair_embed[b * FEAT + f];
        __syncthreads();
        float acc = 0.f;
        #pragma unroll 8
        for (int k = 0; k < FEAT; k++) acc += e[k] * ow1[k * FEAT + f];
        g_preA[b * FEAT + f] = acc;
    } else {
        int r = b - NAPAIR;
        e[f] = relpos_embed[r * FEAT + f];
        __syncthreads();
        float acc = 0.f;
        #pragma unroll 8
        for (int k = 0; k < FEAT; k++) acc += e[k] * ow1[(FEAT + k) * FEAT + f];
        g_preR[r * FEAT + f] = acc;
    }
}

__device__ __forceinline__ float3 f3sub(float3 a, float3 b) { return make_float3(a.x-b.x, a.y-b.y, a.z-b.z); }
__device__ __forceinline__ float3 f3cross(float3 a, float3 b) {
    return make_float3(a.y*b.z - a.z*b.y, a.z*b.x - a.x*b.z, a.x*b.y - a.y*b.x);
}
__device__ __forceinline__ float f3dot(float3 a, float3 b) { return a.x*b.x + a.y*b.y + a.z*b.z; }

__device__ __forceinline__ float dihedral_f(float3 p0, float3 p1, float3 p2, float3 p3) {
    float3 v0 = f3sub(p2, p1), v1 = f3sub(p0, p1), v2 = f3sub(p3, p2);
    float3 u1 = f3cross(v0, v1), u2 = f3cross(v0, v2);
    float nn = f3dot(u1, u1) * f3dot(u2, u2);
    if (!(nn > 0.f)) return 0.f;
    float cosv = f3dot(u1, u2) * rsqrtf(nn);
    cosv = fminf(fmaxf(cosv, -0.999999f), 0.999999f);
    float sd = f3dot(f3cross(v1, v2), v0);
    float sgn = (sd > 0.f) ? 1.f : ((sd < 0.f) ? -1.f : 0.f);
    float d = sgn * acosf(cosv);
    return isfinite(d) ? d : 0.f;
}

__global__ void dihed_kernel(const float* __restrict__ pos) {
    int idx = blockIdx.x * 256 + threadIdx.x;        // NB*L*L threads exactly
    int n = idx >> 16, i = (idx >> 8) & 255, j = idx & 255;
    const float* pi = pos + (size_t)(n * LRES + i) * NATOM * 3;
    const float* pj = pos + (size_t)(n * LRES + j) * NATOM * 3;
    float3 Ni  = make_float3(pi[0], pi[1], pi[2]);
    float3 CAi = make_float3(pi[3], pi[4], pi[5]);
    float3 Ci  = make_float3(pi[6], pi[7], pi[8]);
    float3 Nj  = make_float3(pj[0], pj[1], pj[2]);
    float3 CAj = make_float3(pj[3], pj[4], pj[5]);
    float3 Cj  = make_float3(pj[6], pj[7], pj[8]);
    float phi = dihedral_f(Ci, Nj, CAj, Cj);
    float psi = dihedral_f(Ni, CAi, Ci, Nj);
    g_dihed[(size_t)idx * 2 + 0] = phi;
    g_dihed[(size_t)idx * 2 + 1] = psi;
}

// ---------------- fused main kernel ----------------
// Tile: 64 pairs x 128 feat. 8 warps: warp = (h,g), h=warp>>2 (pair half),
// g=warp&3 (feature quarter). lane -> pair p = h*32+lane; f-range [g*32, g*32+32).
// Activations are k-major: A[k][64]. acc[t] packs (f=fbase+2t, f+1) for pair p.
struct __align__(16) Smem {
    float bufG[MPAIR * 64];   // 50.2KB: stage1 act G; reused for stage3-out etc.
    float bufB[FEAT * 64];    // 32KB ping-pong
    float sW[32 * FEAT];      // 16KB weight chunk
    float wdh[26 * FEAT];     // 13KB dihedral weight rows of out_w1
    float dcode[64 * 26];
    float posI[8 * NATOM * 3];
    float posJ[8 * NATOM * 3];
    float maskI[8 * NATOM];
    float maskJ[8 * NATOM];
    float b1[FEAT]; float b2[FEAT]; float b3[FEAT]; float b4[FEAT]; float b5[FEAT];
    float sc[64]; float mp[64];
    int aap[64]; int rel[64];
    int aaI[8]; int aaJ[8]; int resI[8]; int resJ[8]; int chI[8]; int chJ[8];
};

// acc[p][fbase..fbase+32) += sum_k A[k][p] * W[k][f]
template<int K, int KT>
__device__ __forceinline__ void gemm_acc(const float* __restrict__ Wg,
                                         const float* __restrict__ sAct,
                                         float* __restrict__ sW,
                                         ull acc[16], int tid, int p, int fbase) {
    #pragma unroll 1
    for (int k0 = 0; k0 < K; k0 += KT) {
        __syncthreads();
        const float4* src = (const float4*)(Wg + k0 * FEAT);
        float4* dst = (float4*)sW;
        #pragma unroll
        for (int idx = tid; idx < KT * 32; idx += 256) dst[idx] = src[idx];
        __syncthreads();
        #pragma unroll 4
        for (int kk = 0; kk < KT; kk++) {
            float a = sAct[(k0 + kk) * 64 + p];
            ull av = pack2(a, a);
            const ulonglong2* wr = (const ulonglong2*)(sW + kk * FEAT + fbase);
            #pragma unroll
            for (int q = 0; q < 8; q++) {
                ulonglong2 w2 = wr[q];
                fma2(acc[2 * q],     av, w2.x);
                fma2(acc[2 * q + 1], av, w2.y);
            }
        }
    }
}

// relu(acc + bias) -> dst in k-major layout dst[f][p]
__device__ __forceinline__ void epilogue(ull acc[16], const float* __restrict__ bias,
                                         float* __restrict__ dst, int p, int fbase) {
    #pragma unroll
    for (int t = 0; t < 16; t++) {
        float2 v = unpack2(acc[t]);
        int f = fbase + 2 * t;
        dst[f * 64 + p]       = fmaxf(v.x + bias[f], 0.f);
        dst[(f + 1) * 64 + p] = fmaxf(v.y + bias[f + 1], 0.f);
    }
}

__global__ void __launch_bounds__(256, 1)
fused_kernel(const int* __restrict__ aa, const int* __restrict__ res_nb,
             const int* __restrict__ chain_nb, const float* __restrict__ pos,
             const float* __restrict__ mask,
             const float* __restrict__ dw1, const float* __restrict__ db1,
             const float* __restrict__ dw2, const float* __restrict__ db2,
             const float* __restrict__ ow1, const float* __restrict__ ob1,
             const float* __restrict__ ow2, const float* __restrict__ ob2,
             const float* __restrict__ ow3, const float* __restrict__ ob3,
             float* __restrict__ outp) {
    extern __shared__ char smem_raw[];
    Smem& s = *reinterpret_cast<Smem*>(smem_raw);
    const int tid = threadIdx.x;
    const int warp = tid >> 5, lane = tid & 31;
    const int fbase = (warp & 3) * 32;
    const int p = (warp >> 2) * 32 + lane;
    const int bid = blockIdx.x;
    const int n  = bid >> 10;
    const int i0 = ((bid >> 5) & 31) * 8;
    const int j0 = (bid & 31) * 8;

    // ---- phase 0: cooperative loads ----
    {
        const float* pbI = pos + (size_t)(n * LRES + i0) * NATOM * 3;
        const float* pbJ = pos + (size_t)(n * LRES + j0) * NATOM * 3;
        for (int idx = tid; idx < 8 * NATOM * 3; idx += 256) { s.posI[idx] = pbI[idx]; s.posJ[idx] = pbJ[idx]; }
        const float* mbI = mask + (size_t)(n * LRES + i0) * NATOM;
        const float* mbJ = mask + (size_t)(n * LRES + j0) * NATOM;
        if (tid < 8 * NATOM) { s.maskI[tid] = mbI[tid]; s.maskJ[tid] = mbJ[tid]; }
        if (tid < 8) {
            s.aaI[tid]  = aa[n * LRES + i0 + tid];  s.aaJ[tid]  = aa[n * LRES + j0 + tid];
            s.resI[tid] = res_nb[n * LRES + i0 + tid]; s.resJ[tid] = res_nb[n * LRES + j0 + tid];
            s.chI[tid]  = chain_nb[n * LRES + i0 + tid]; s.chJ[tid] = chain_nb[n * LRES + j0 + tid];
        }
        if (tid < 128) {
            s.b1[tid] = db1[tid]; s.b2[tid] = db2[tid]; s.b3[tid] = ob1[tid];
            s.b4[tid] = ob2[tid]; s.b5[tid] = ob3[tid];
        }
        for (int idx = tid; idx < 26 * FEAT; idx += 256) s.wdh[idx] = ow1[384 * FEAT + idx];
    }
    __syncthreads();

    // ---- phase 0b: per-pair meta + dihedral angular codes ----
    if (tid < 64) {
        int ii = tid >> 3, jj = tid & 7;
        s.aap[tid] = s.aaI[ii] * MAXAA + s.aaJ[jj];
        int r = s.resI[ii] - s.resJ[jj];
        s.rel[tid] = min(max(r, -32), 32) + 32;
        s.sc[tid] = (s.chI[ii] == s.chJ[jj]) ? 1.f : 0.f;
        s.mp[tid] = s.maskI[ii * NATOM + 1] * s.maskJ[jj * NATOM + 1];   // CA masks
        const float* dh = &g_dihed[((size_t)(n * LRES + i0 + ii) * LRES + (j0 + jj)) * 2];
        float phi = dh[0], psi = dh[1];
        float* c = &s.dcode[tid * 26];
        const float FRQ[6] = {1.f, 2.f, 3.f, 1.f, 0.5f, 1.f / 3.f};
        c[0] = phi; c[13] = psi;
        #pragma unroll
        for (int t = 0; t < 6; t++) {
            float sv, cv;
            sincosf(phi * FRQ[t], &sv, &cv); c[1 + t]  = sv; c[7 + t]  = cv;
            sincosf(psi * FRQ[t], &sv, &cv); c[14 + t] = sv; c[20 + t] = cv;
        }
    }
    __syncthreads();

    // ---- phase 1: masked gaussian distance features, k-major G[m][p] ----
    for (int idx = tid; idx < 64 * MPAIR; idx += 256) {
        int m = idx >> 6;
        int pp = idx & 63;
        int a = m / NATOM;
        int b = m - a * NATOM;
        int ii = pp >> 3, jj = pp & 7;
        float dx = s.posI[ii * 42 + a * 3 + 0] - s.posJ[jj * 42 + b * 3 + 0];
        float dy = s.posI[ii * 42 + a * 3 + 1] - s.posJ[jj * 42 + b * 3 + 1];
        float dz = s.posI[ii * 42 + a * 3 + 2] - s.posJ[jj * 42 + b * 3 + 2];
        float ss = dx * dx + dy * dy + dz * dz;        // (10*d)^2
        float cc = g_softc[s.aap[pp] * MPAIR + m];
        float g = __expf(-cc * ss * 0.01f) * (s.maskI[ii * NATOM + a] * s.maskJ[jj * NATOM + b]);
        s.bufG[idx] = g;
    }
    // gemm's leading __syncthreads covers bufG visibility

    ull acc[16];

    // ---- stage 1: h1 = relu(G @ dist_w1 + b1) -> bufB ----
    #pragma unroll
    for (int q = 0; q < 16; q++) acc[q] = 0ull;
    gemm_acc<MPAIR, 28>(dw1, s.bufG, s.sW, acc, tid, p, fbase);
    epilogue(acc, s.b1, s.bufB, p, fbase);

    // ---- stage 2: fd = relu(h1 @ dist_w2 + b2) -> bufG ----
    #pragma unroll
    for (int q = 0; q < 16; q++) acc[q] = 0ull;
    gemm_acc<FEAT, 32>(dw2, s.bufB, s.sW, acc, tid, p, fbase);
    epilogue(acc, s.b2, s.bufG, p, fbase);

    // ---- stage 3: h = relu(preA + sc*preR + dihed@Wdh + fd@Wdist + ob1) -> bufB ----
    {
        int ap = s.aap[p], rl = s.rel[p];
        float scv = s.sc[p];
        const float4* A4 = (const float4*)&g_preA[ap * FEAT + fbase];
        const float4* R4 = (const float4*)&g_preR[rl * FEAT + fbase];
        #pragma unroll
        for (int q = 0; q < 8; q++) {
            float4 a4 = A4[q], r4 = R4[q];
            acc[2 * q]     = pack2(a4.x + scv * r4.x, a4.y + scv * r4.y);
            acc[2 * q + 1] = pack2(a4.z + scv * r4.z, a4.w + scv * r4.w);
        }
        #pragma unroll
        for (int t = 0; t < 26; t++) {
            float d = s.dcode[p * 26 + t];
            ull av = pack2(d, d);
            const ulonglong2* wr = (const ulonglong2*)(s.wdh + t * FEAT + fbase);
            #pragma unroll
            for (int q = 0; q < 8; q++) {
                ulonglong2 w2 = wr[q];
                fma2(acc[2 * q],     av, w2.x);
                fma2(acc[2 * q + 1], av, w2.y);
            }
        }
    }
    gemm_acc<FEAT, 32>(ow1 + 256 * FEAT, s.bufG, s.sW, acc, tid, p, fbase);
    epilogue(acc, s.b3, s.bufB, p, fbase);

    // ---- stage 4: h = relu(h @ out_w2 + ob2) -> bufG ----
    #pragma unroll
    for (int q = 0; q < 16; q++) acc[q] = 0ull;
    gemm_acc<FEAT, 32>(ow2, s.bufB, s.sW, acc, tid, p, fbase);
    epilogue(acc, s.b4, s.bufG, p, fbase);

    // ---- stage 5: out = (h @ out_w3 + ob3) * mask_pair -> global ----
    #pragma unroll
    for (int q = 0; q < 16; q++) acc[q] = 0ull;
    gemm_acc<FEAT, 32>(ow3, s.bufG, s.sW, acc, tid, p, fbase);
    {
        int ii = p >> 3, jj = p & 7;
        float mpv = s.mp[p];
        float* orow = outp + ((((size_t)n * LRES + (i0 + ii)) * LRES + (j0 + jj)) * FEAT + fbase);
        #pragma unroll
        for (int q = 0; q < 8; q++) {
            float2 v0 = unpack2(acc[2 * q]);
            float2 v1 = unpack2(acc[2 * q + 1]);
            int f = fbase + 4 * q;
            float4 o = make_float4((v0.x + s.b5[f])     * mpv,
                                   (v0.y + s.b5[f + 1]) * mpv,
                                   (v1.x + s.b5[f + 2]) * mpv,
                                   (v1.y + s.b5[f + 3]) * mpv);
            *(float4*)&orow[4 * q] = o;
        }
    }
}

// ---------------- launch ----------------
extern "C" void kernel_launch(void* const* d_in, const int* in_sizes, int n_in,
                              void* d_out, int out_size) {
    const int*   aa        = (const int*)  d_in[0];
    const int*   res_nb    = (const int*)  d_in[1];
    const int*   chain_nb  = (const int*)  d_in[2];
    const float* pos       = (const float*)d_in[3];
    const float* mask      = (const float*)d_in[4];
    const float* aap_embed = (const float*)d_in[5];
    const float* rel_embed = (const float*)d_in[6];
    const float* distcoef  = (const float*)d_in[7];
    const float* dw1 = (const float*)d_in[8];
    const float* db1 = (const float*)d_in[9];
    const float* dw2 = (const float*)d_in[10];
    const float* db2 = (const float*)d_in[11];
    const float* ow1 = (const float*)d_in[12];
    const float* ob1 = (const float*)d_in[13];
    const float* ow2 = (const float*)d_in[14];
    const float* ob2 = (const float*)d_in[15];
    const float* ow3 = (const float*)d_in[16];
    const float* ob3 = (const float*)d_in[17];
    float* outp = (float*)d_out;

    cudaFuncSetAttribute(fused_kernel, cudaFuncAttributeMaxDynamicSharedMemorySize,
                         (int)sizeof(Smem));

    softc_kernel<<<(NAPAIR * MPAIR + 255) / 256, 256>>>(distcoef);
    pretab_kernel<<<NAPAIR + NREL, 128>>>(aap_embed, rel_embed, ow1);
    dihed_kernel<<<(NBATCH * LRES * LRES) / 256, 256>>>(pos);
    fused_kernel<<<NBATCH * 32 * 32, 256, sizeof(Smem)>>>(
        aa, res_nb, chain_nb, pos, mask,
        dw1, db1, dw2, db2, ow1, ob1, ow2, ob2, ow3, ob3, outp);
}

// round 5
// speedup vs baseline: 1.4897x; 1.3850x over previous
#include <cuda_runtime.h>
#include <cstdint>

#define NBATCH 4
#define LRES   256
#define NATOM  14
#define FEAT   128
#define MPAIR  196      // NATOM*NATOM
#define MAXAA  22
#define NAPAIR 484      // MAXAA*MAXAA
#define NREL   65
#define TPAIR  128      // pairs per block tile (8 i-rows x 16 j-cols)

typedef unsigned long long ull;

// ---------------- scratch (static __device__ — no allocations allowed) ----------------
__device__ float g_softc[NAPAIR * MPAIR];          // softplus(distcoef_embed)
__device__ float g_preA [NAPAIR * FEAT];           // aa_pair_embed @ out_w1[0:128]
__device__ float g_preR [NREL   * FEAT];           // relpos_embed  @ out_w1[128:256]
__device__ float g_dihed[NBATCH * LRES * LRES * 2];// (phi, psi) per pair

// ---------------- packed f32x2 helpers ----------------
__device__ __forceinline__ ull pack2(float lo, float hi) {
    ull r; asm("mov.b64 %0, {%1, %2};" : "=l"(r) : "f"(lo), "f"(hi)); return r;
}
__device__ __forceinline__ void fma2(ull& d, ull a, ull b) {
    asm("fma.rn.f32x2 %0, %1, %2, %0;" : "+l"(d) : "l"(a), "l"(b));
}
__device__ __forceinline__ float2 unpack2(ull v) {
    float2 r; asm("mov.b64 {%0, %1}, %2;" : "=f"(r.x), "=f"(r.y) : "l"(v)); return r;
}

// ---------------- small precompute kernels ----------------
__global__ void softc_kernel(const float* __restrict__ distcoef) {
    int idx = blockIdx.x * 256 + threadIdx.x;
    if (idx < NAPAIR * MPAIR) {
        float x = distcoef[idx];
        g_softc[idx] = (x > 20.f) ? x : log1pf(expf(x));
    }
}

__global__ void pretab_kernel(const float* __restrict__ aa_pair_embed,
                              const float* __restrict__ relpos_embed,
                              const float* __restrict__ ow1) {
    __shared__ float e[FEAT];
    int b = blockIdx.x, f = threadIdx.x;
    if (b < NAPAIR) {
        e[f] = aa_pair_embed[b * FEAT + f];
        __syncthreads();
        float acc = 0.f;
        #pragma unroll 8
        for (int k = 0; k < FEAT; k++) acc += e[k] * ow1[k * FEAT + f];
        g_preA[b * FEAT + f] = acc;
    } else {
        int r = b - NAPAIR;
        e[f] = relpos_embed[r * FEAT + f];
        __syncthreads();
        float acc = 0.f;
        #pragma unroll 8
        for (int k = 0; k < FEAT; k++) acc += e[k] * ow1[(FEAT + k) * FEAT + f];
        g_preR[r * FEAT + f] = acc;
    }
}

__device__ __forceinline__ float3 f3sub(float3 a, float3 b) { return make_float3(a.x-b.x, a.y-b.y, a.z-b.z); }
__device__ __forceinline__ float3 f3cross(float3 a, float3 b) {
    return make_float3(a.y*b.z - a.z*b.y, a.z*b.x - a.x*b.z, a.x*b.y - a.y*b.x);
}
__device__ __forceinline__ float f3dot(float3 a, float3 b) { return a.x*b.x + a.y*b.y + a.z*b.z; }

__device__ __forceinline__ float dihedral_f(float3 p0, float3 p1, float3 p2, float3 p3) {
    float3 v0 = f3sub(p2, p1), v1 = f3sub(p0, p1), v2 = f3sub(p3, p2);
    float3 u1 = f3cross(v0, v1), u2 = f3cross(v0, v2);
    float nn = f3dot(u1, u1) * f3dot(u2, u2);
    if (!(nn > 0.f)) return 0.f;
    float cosv = f3dot(u1, u2) * rsqrtf(nn);
    cosv = fminf(fmaxf(cosv, -0.999999f), 0.999999f);
    float sd = f3dot(f3cross(v1, v2), v0);
    float sgn = (sd > 0.f) ? 1.f : ((sd < 0.f) ? -1.f : 0.f);
    float d = sgn * acosf(cosv);
    return isfinite(d) ? d : 0.f;
}

__global__ void dihed_kernel(const float* __restrict__ pos) {
    int idx = blockIdx.x * 256 + threadIdx.x;        // NB*L*L threads exactly
    int n = idx >> 16, i = (idx >> 8) & 255, j = idx & 255;
    const float* pi = pos + (size_t)(n * LRES + i) * NATOM * 3;
    const float* pj = pos + (size_t)(n * LRES + j) * NATOM * 3;
    float3 Ni  = make_float3(pi[0], pi[1], pi[2]);
    float3 CAi = make_float3(pi[3], pi[4], pi[5]);
    float3 Ci  = make_float3(pi[6], pi[7], pi[8]);
    float3 Nj  = make_float3(pj[0], pj[1], pj[2]);
    float3 CAj = make_float3(pj[3], pj[4], pj[5]);
    float3 Cj  = make_float3(pj[6], pj[7], pj[8]);
    float phi = dihedral_f(Ci, Nj, CAj, Cj);
    float psi = dihedral_f(Ni, CAi, Ci, Nj);
    g_dihed[(size_t)idx * 2 + 0] = phi;
    g_dihed[(size_t)idx * 2 + 1] = psi;
}

// ---------------- fused main kernel ----------------
// Tile: 128 pairs (8 i x 16 j) x 128 feat. 8 warps: g=warp&3 -> feature quarter
// [g*32, g*32+32); h=warp>>2 -> pair half. Each thread owns pairs p0=h*64+lane
// and p1=p0+32 with 2x16 packed-f32x2 accumulators. Activations k-major A[k][128].
struct __align__(16) Smem {
    float bufG[MPAIR * TPAIR];  // 100.4KB: stage1 act G; reused for stage3-out etc.
    float bufB[FEAT * TPAIR];   // 64KB ping-pong
    float sW[32 * FEAT];        // 16KB weight chunk
    float wdh[26 * FEAT];       // 13KB dihedral weight rows of out_w1
    float dcode[TPAIR * 26];    // 13.3KB
    float posI[8 * NATOM * 3];
    float posJ[16 * NATOM * 3];
    float maskI[8 * NATOM];
    float maskJ[16 * NATOM];
    float b1[FEAT]; float b2[FEAT]; float b3[FEAT]; float b4[FEAT]; float b5[FEAT];
    float sc[TPAIR]; float mp[TPAIR];
    int aap[TPAIR]; int rel[TPAIR];
    int aaI[8]; int aaJ[16]; int resI[8]; int resJ[16]; int chI[8]; int chJ[16];
};

// accA/accB[p][fbase..fbase+32) += sum_k A[k][p] * W[k][f], weight chunks
// double-buffered through registers (prefetch next chunk during compute-store).
template<int K>
__device__ __forceinline__ void gemm_acc(const float* __restrict__ Wg,
                                         const float* __restrict__ sAct,
                                         float* __restrict__ sW,
                                         ull accA[16], ull accB[16],
                                         int tid, int p0, int p1, int fbase) {
    constexpr int NCH = (K + 31) / 32;
    float4 r0, r1, r2, r3;
    {   // prefetch chunk 0
        const float4* src = (const float4*)Wg;
        constexpr int lim = (K < 32 ? K : 32) * 32;
        if (tid < lim)       r0 = src[tid];
        if (tid + 256 < lim) r1 = src[tid + 256];
        if (tid + 512 < lim) r2 = src[tid + 512];
        if (tid + 768 < lim) r3 = src[tid + 768];
    }
    #pragma unroll 1
    for (int c = 0; c < NCH; c++) {
        const int k0 = c * 32;
        const int rows = (K - k0 < 32) ? (K - k0) : 32;
        __syncthreads();
        {   // commit prefetched chunk to smem
            float4* dst = (float4*)sW;
            const int lim = rows * 32;
            if (tid < lim)       dst[tid] = r0;
            if (tid + 256 < lim) dst[tid + 256] = r1;
            if (tid + 512 < lim) dst[tid + 512] = r2;
            if (tid + 768 < lim) dst[tid + 768] = r3;
        }
        if (c + 1 < NCH) {  // prefetch next chunk
            const float4* src = (const float4*)(Wg + (k0 + 32) * FEAT);
            const int lim = ((K - k0 - 32 < 32) ? (K - k0 - 32) : 32) * 32;
            if (tid < lim)       r0 = src[tid];
            if (tid + 256 < lim) r1 = src[tid + 256];
            if (tid + 512 < lim) r2 = src[tid + 512];
            if (tid + 768 < lim) r3 = src[tid + 768];
        }
        __syncthreads();
        if (rows == 32) {
            #pragma unroll 4
            for (int kk = 0; kk < 32; kk++) {
                const float* arow = sAct + (k0 + kk) * TPAIR;
                float a0 = arow[p0], a1 = arow[p1];
                ull av0 = pack2(a0, a0), av1 = pack2(a1, a1);
                const ulonglong2* wr = (const ulonglong2*)(sW + kk * FEAT + fbase);
                #pragma unroll
                for (int q = 0; q < 8; q++) {
                    ulonglong2 w2 = wr[q];
                    fma2(accA[2 * q],     av0, w2.x);
                    fma2(accA[2 * q + 1], av0, w2.y);
                    fma2(accB[2 * q],     av1, w2.x);
                    fma2(accB[2 * q + 1], av1, w2.y);
                }
            }
        } else {
            for (int kk = 0; kk < rows; kk++) {
                const float* arow = sAct + (k0 + kk) * TPAIR;
                float a0 = arow[p0], a1 = arow[p1];
                ull av0 = pack2(a0, a0), av1 = pack2(a1, a1);
                const ulonglong2* wr = (const ulonglong2*)(sW + kk * FEAT + fbase);
                #pragma unroll
                for (int q = 0; q < 8; q++) {
                    ulonglong2 w2 = wr[q];
                    fma2(accA[2 * q],     av0, w2.x);
                    fma2(accA[2 * q + 1], av0, w2.y);
                    fma2(accB[2 * q],     av1, w2.x);
                    fma2(accB[2 * q + 1], av1, w2.y);
                }
            }
        }
    }
}

// relu(acc + bias) -> dst in k-major layout dst[f][p]
__device__ __forceinline__ void epilogue(ull accA[16], ull accB[16],
                                         const float* __restrict__ bias,
                                         float* __restrict__ dst, int p0, int p1, int fbase) {
    #pragma unroll
    for (int t = 0; t < 16; t++) {
        float2 va = unpack2(accA[t]);
        float2 vb = unpack2(accB[t]);
        int f = fbase + 2 * t;
        float bx = bias[f], by = bias[f + 1];
        dst[f * TPAIR + p0]       = fmaxf(va.x + bx, 0.f);
        dst[(f + 1) * TPAIR + p0] = fmaxf(va.y + by, 0.f);
        dst[f * TPAIR + p1]       = fmaxf(vb.x + bx, 0.f);
        dst[(f + 1) * TPAIR + p1] = fmaxf(vb.y + by, 0.f);
    }
}

__global__ void __launch_bounds__(256, 1)
fused_kernel(const int* __restrict__ aa, const int* __restrict__ res_nb,
             const int* __restrict__ chain_nb, const float* __restrict__ pos,
             const float* __restrict__ mask,
             const float* __restrict__ dw1, const float* __restrict__ db1,
             const float* __restrict__ dw2, const float* __restrict__ db2,
             const float* __restrict__ ow1, const float* __restrict__ ob1,
             const float* __restrict__ ow2, const float* __restrict__ ob2,
             const float* __restrict__ ow3, const float* __restrict__ ob3,
             float* __restrict__ outp) {
    extern __shared__ char smem_raw[];
    Smem& s = *reinterpret_cast<Smem*>(smem_raw);
    const int tid = threadIdx.x;
    const int warp = tid >> 5, lane = tid & 31;
    const int fbase = (warp & 3) * 32;
    const int p0 = (warp >> 2) * 64 + lane;
    const int p1 = p0 + 32;
    const int bid = blockIdx.x;
    const int n  = bid >> 9;                 // 32*16 tiles per batch
    const int i0 = ((bid >> 4) & 31) * 8;
    const int j0 = (bid & 15) * 16;

    // ---- phase 0: cooperative loads ----
    {
        const float* pbI = pos + (size_t)(n * LRES + i0) * NATOM * 3;
        const float* pbJ = pos + (size_t)(n * LRES + j0) * NATOM * 3;
        for (int idx = tid; idx < 8 * NATOM * 3; idx += 256)  s.posI[idx] = pbI[idx];
        for (int idx = tid; idx < 16 * NATOM * 3; idx += 256) s.posJ[idx] = pbJ[idx];
        const float* mbI = mask + (size_t)(n * LRES + i0) * NATOM;
        const float* mbJ = mask + (size_t)(n * LRES + j0) * NATOM;
        if (tid < 8 * NATOM)  s.maskI[tid] = mbI[tid];
        if (tid < 16 * NATOM) s.maskJ[tid] = mbJ[tid];
        if (tid < 8) {
            s.aaI[tid]  = aa[n * LRES + i0 + tid];
            s.resI[tid] = res_nb[n * LRES + i0 + tid];
            s.chI[tid]  = chain_nb[n * LRES + i0 + tid];
        }
        if (tid >= 32 && tid < 48) {
            int t = tid - 32;
            s.aaJ[t]  = aa[n * LRES + j0 + t];
            s.resJ[t] = res_nb[n * LRES + j0 + t];
            s.chJ[t]  = chain_nb[n * LRES + j0 + t];
        }
        if (tid < 128) {
            s.b1[tid] = db1[tid]; s.b2[tid] = db2[tid]; s.b3[tid] = ob1[tid];
            s.b4[tid] = ob2[tid]; s.b5[tid] = ob3[tid];
        }
        for (int idx = tid; idx < 26 * FEAT; idx += 256) s.wdh[idx] = ow1[384 * FEAT + idx];
    }
    __syncthreads();

    // ---- phase 0b: per-pair meta + dihedral angular codes ----
    if (tid < TPAIR) {
        int ii = tid >> 4, jj = tid & 15;
        s.aap[tid] = s.aaI[ii] * MAXAA + s.aaJ[jj];
        int r = s.resI[ii] - s.resJ[jj];
        s.rel[tid] = min(max(r, -32), 32) + 32;
        s.sc[tid] = (s.chI[ii] == s.chJ[jj]) ? 1.f : 0.f;
        s.mp[tid] = s.maskI[ii * NATOM + 1] * s.maskJ[jj * NATOM + 1];   // CA masks
        const float* dh = &g_dihed[((size_t)(n * LRES + i0 + ii) * LRES + (j0 + jj)) * 2];
        float phi = dh[0], psi = dh[1];
        float* c = &s.dcode[tid * 26];
        const float FRQ[6] = {1.f, 2.f, 3.f, 1.f, 0.5f, 1.f / 3.f};
        c[0] = phi; c[13] = psi;
        #pragma unroll
        for (int t = 0; t < 6; t++) {
            float sv, cv;
            sincosf(phi * FRQ[t], &sv, &cv); c[1 + t]  = sv; c[7 + t]  = cv;
            sincosf(psi * FRQ[t], &sv, &cv); c[14 + t] = sv; c[20 + t] = cv;
        }
    }
    __syncthreads();

    // ---- phase 1: masked gaussian distance features, k-major G[m][p] ----
    for (int idx = tid; idx < TPAIR * MPAIR; idx += 256) {
        int m = idx >> 7;
        int pp = idx & (TPAIR - 1);
        int a = m / NATOM;
        int b = m - a * NATOM;
        int ii = pp >> 4, jj = pp & 15;
        float dx = s.posI[ii * 42 + a * 3 + 0] - s.posJ[jj * 42 + b * 3 + 0];
        float dy = s.posI[ii * 42 + a * 3 + 1] - s.posJ[jj * 42 + b * 3 + 1];
        float dz = s.posI[ii * 42 + a * 3 + 2] - s.posJ[jj * 42 + b * 3 + 2];
        float ss = dx * dx + dy * dy + dz * dz;        // (10*d)^2
        float cc = g_softc[s.aap[pp] * MPAIR + m];
        float g = __expf(-cc * ss * 0.01f) * (s.maskI[ii * NATOM + a] * s.maskJ[jj * NATOM + b]);
        s.bufG[idx] = g;
    }
    // gemm's leading __syncthreads covers bufG visibility

    ull accA[16], accB[16];

    // ---- stage 1: h1 = relu(G @ dist_w1 + b1) -> bufB ----
    #pragma unroll
    for (int q = 0; q < 16; q++) { accA[q] = 0ull; accB[q] = 0ull; }
    gemm_acc<MPAIR>(dw1, s.bufG, s.sW, accA, accB, tid, p0, p1, fbase);
    epilogue(accA, accB, s.b1, s.bufB, p0, p1, fbase);

    // ---- stage 2: fd = relu(h1 @ dist_w2 + b2) -> bufG ----
    #pragma unroll
    for (int q = 0; q < 16; q++) { accA[q] = 0ull; accB[q] = 0ull; }
    gemm_acc<FEAT>(dw2, s.bufB, s.sW, accA, accB, tid, p0, p1, fbase);
    epilogue(accA, accB, s.b2, s.bufG, p0, p1, fbase);

    // ---- stage 3: h = relu(preA + sc*preR + dihed@Wdh + fd@Wdist + ob1) -> bufB ----
    {
        int ap0 = s.aap[p0], rl0 = s.rel[p0];
        int ap1 = s.aap[p1], rl1 = s.rel[p1];
        float sc0 = s.sc[p0], sc1 = s.sc[p1];
        const float4* A0 = (const float4*)&g_preA[ap0 * FEAT + fbase];
        const float4* R0 = (const float4*)&g_preR[rl0 * FEAT + fbase];
        const float4* A1 = (const float4*)&g_preA[ap1 * FEAT + fbase];
        const float4* R1 = (const float4*)&g_preR[rl1 * FEAT + fbase];
        #pragma unroll
        for (int q = 0; q < 8; q++) {
            float4 a4 = A0[q], r4 = R0[q];
            accA[2 * q]     = pack2(a4.x + sc0 * r4.x, a4.y + sc0 * r4.y);
            accA[2 * q + 1] = pack2(a4.z + sc0 * r4.z, a4.w + sc0 * r4.w);
            float4 b4v = A1[q], q4 = R1[q];
            accB[2 * q]     = pack2(b4v.x + sc1 * q4.x, b4v.y + sc1 * q4.y);
            accB[2 * q + 1] = pack2(b4v.z + sc1 * q4.z, b4v.w + sc1 * q4.w);
        }
        #pragma unroll
        for (int t = 0; t < 26; t++) {
            float d0 = s.dcode[p0 * 26 + t];
            float d1 = s.dcode[p1 * 26 + t];
            ull av0 = pack2(d0, d0), av1 = pack2(d1, d1);
            const ulonglong2* wr = (const ulonglong2*)(s.wdh + t * FEAT + fbase);
            #pragma unroll
            for (int q = 0; q < 8; q++) {
                ulonglong2 w2 = wr[q];
                fma2(accA[2 * q],     av0, w2.x);
                fma2(accA[2 * q + 1], av0, w2.y);
                fma2(accB[2 * q],     av1, w2.x);
                fma2(accB[2 * q + 1], av1, w2.y);
            }
        }
    }
    gemm_acc<FEAT>(ow1 + 256 * FEAT, s.bufG, s.sW, accA, accB, tid, p0, p1, fbase);
    epilogue(accA, accB, s.b3, s.bufB, p0, p1, fbase);

    // ---- stage 4: h = relu(h @ out_w2 + ob2) -> bufG ----
    #pragma unroll
    for (int q = 0; q < 16; q++) { accA[q] = 0ull; accB[q] = 0ull; }
    gemm_acc<FEAT>(ow2, s.bufB, s.sW, accA, accB, tid, p0, p1, fbase);
    epilogue(accA, accB, s.b4, s.bufG, p0, p1, fbase);

    // ---- stage 5: out = (h @ out_w3 + ob3) * mask_pair -> global ----
    #pragma unroll
    for (int q = 0; q < 16; q++) { accA[q] = 0ull; accB[q] = 0ull; }
    gemm_acc<FEAT>(ow3, s.bufG, s.sW, accA, accB, tid, p0, p1, fbase);
    #pragma unroll
    for (int half = 0; half < 2; half++) {
        ull* acc = half ? accB : accA;
        int p = half ? p1 : p0;
        int ii = p >> 4, jj = p & 15;
        float mpv = s.mp[p];
        float* orow = outp + ((((size_t)n * LRES + (i0 + ii)) * LRES + (j0 + jj)) * FEAT + fbase);
        #pragma unroll
        for (int q = 0; q < 8; q++) {
            float2 v0 = unpack2(acc[2 * q]);
            float2 v1 = unpack2(acc[2 * q + 1]);
            int f = fbase + 4 * q;
            float4 o = make_float4((v0.x + s.b5[f])     * mpv,
                                   (v0.y + s.b5[f + 1]) * mpv,
                                   (v1.x + s.b5[f + 2]) * mpv,
                                   (v1.y + s.b5[f + 3]) * mpv);
            *(float4*)&orow[4 * q] = o;
        }
    }
}

// ---------------- launch ----------------
extern "C" void kernel_launch(void* const* d_in, const int* in_sizes, int n_in,
                              void* d_out, int out_size) {
    const int*   aa        = (const int*)  d_in[0];
    const int*   res_nb    = (const int*)  d_in[1];
    const int*   chain_nb  = (const int*)  d_in[2];
    const float* pos       = (const float*)d_in[3];
    const float* mask      = (const float*)d_in[4];
    const float* aap_embed = (const float*)d_in[5];
    const float* rel_embed = (const float*)d_in[6];
    const float* distcoef  = (const float*)d_in[7];
    const float* dw1 = (const float*)d_in[8];
    const float* db1 = (const float*)d_in[9];
    const float* dw2 = (const float*)d_in[10];
    const float* db2 = (const float*)d_in[11];
    const float* ow1 = (const float*)d_in[12];
    const float* ob1 = (const float*)d_in[13];
    const float* ow2 = (const float*)d_in[14];
    const float* ob2 = (const float*)d_in[15];
    const float* ow3 = (const float*)d_in[16];
    const float* ob3 = (const float*)d_in[17];
    float* outp = (float*)d_out;

    cudaFuncSetAttribute(fused_kernel, cudaFuncAttributeMaxDynamicSharedMemorySize,
                         (int)sizeof(Smem));

    softc_kernel<<<(NAPAIR * MPAIR + 255) / 256, 256>>>(distcoef);
    pretab_kernel<<<NAPAIR + NREL, 128>>>(aap_embed, rel_embed, ow1);
    dihed_kernel<<<(NBATCH * LRES * LRES) / 256, 256>>>(pos);
    fused_kernel<<<NBATCH * 32 * 16, 256, sizeof(Smem)>>>(
        aa, res_nb, chain_nb, pos, mask,
        dw1, db1, dw2, db2, ow1, ob1, ow2, ob2, ow3, ob3, outp);
}

// round 7
// speedup vs baseline: 1.6247x; 1.0906x over previous
#include <cuda_runtime.h>
#include <cstdint>

#define NBATCH 4
#define LRES   256
#define NATOM  14
#define FEAT   128
#define MPAIR  196      // NATOM*NATOM
#define MAXAA  22
#define NAPAIR 484      // MAXAA*MAXAA
#define NREL   65
#define TPAIR  128      // pairs per block tile (8 i-rows x 16 j-cols)
#define NTHREADS 512

typedef unsigned long long ull;

// ---------------- scratch (static __device__ — no allocations allowed) ----------------
__device__ float g_softc[NAPAIR * MPAIR];          // softplus(distcoef_embed)
__device__ float g_preA [NAPAIR * FEAT];           // aa_pair_embed @ out_w1[0:128]
__device__ float g_preR [NREL   * FEAT];           // relpos_embed  @ out_w1[128:256]
__device__ float g_dihed[NBATCH * LRES * LRES * 2];// (phi, psi) per pair

// ---------------- packed f32x2 helpers ----------------
__device__ __forceinline__ ull pack2(float lo, float hi) {
    ull r; asm("mov.b64 %0, {%1, %2};" : "=l"(r) : "f"(lo), "f"(hi)); return r;
}
__device__ __forceinline__ void fma2(ull& d, ull a, ull b) {
    asm("fma.rn.f32x2 %0, %1, %2, %0;" : "+l"(d) : "l"(a), "l"(b));
}
__device__ __forceinline__ float2 unpack2(ull v) {
    float2 r; asm("mov.b64 {%0, %1}, %2;" : "=f"(r.x), "=f"(r.y) : "l"(v)); return r;
}

// ---------------- small precompute kernels ----------------
__global__ void softc_kernel(const float* __restrict__ distcoef) {
    int idx = blockIdx.x * 256 + threadIdx.x;
    if (idx < NAPAIR * MPAIR) {
        float x = distcoef[idx];
        g_softc[idx] = (x > 20.f) ? x : log1pf(expf(x));
    }
}

__global__ void pretab_kernel(const float* __restrict__ aa_pair_embed,
                              const float* __restrict__ relpos_embed,
                              const float* __restrict__ ow1) {
    __shared__ float e[FEAT];
    int b = blockIdx.x, f = threadIdx.x;
    if (b < NAPAIR) {
        e[f] = aa_pair_embed[b * FEAT + f];
        __syncthreads();
        float acc = 0.f;
        #pragma unroll 8
        for (int k = 0; k < FEAT; k++) acc += e[k] * ow1[k * FEAT + f];
        g_preA[b * FEAT + f] = acc;
    } else {
        int r = b - NAPAIR;
        e[f] = relpos_embed[r * FEAT + f];
        __syncthreads();
        float acc = 0.f;
        #pragma unroll 8
        for (int k = 0; k < FEAT; k++) acc += e[k] * ow1[(FEAT + k) * FEAT + f];
        g_preR[r * FEAT + f] = acc;
    }
}

__device__ __forceinline__ float3 f3sub(float3 a, float3 b) { return make_float3(a.x-b.x, a.y-b.y, a.z-b.z); }
__device__ __forceinline__ float3 f3cross(float3 a, float3 b) {
    return make_float3(a.y*b.z - a.z*b.y, a.z*b.x - a.x*b.z, a.x*b.y - a.y*b.x);
}
__device__ __forceinline__ float f3dot(float3 a, float3 b) { return a.x*b.x + a.y*b.y + a.z*b.z; }

__device__ __forceinline__ float dihedral_f(float3 p0, float3 p1, float3 p2, float3 p3) {
    float3 v0 = f3sub(p2, p1), v1 = f3sub(p0, p1), v2 = f3sub(p3, p2);
    float3 u1 = f3cross(v0, v1), u2 = f3cross(v0, v2);
    float nn = f3dot(u1, u1) * f3dot(u2, u2);
    if (!(nn > 0.f)) return 0.f;
    float cosv = f3dot(u1, u2) * rsqrtf(nn);
    cosv = fminf(fmaxf(cosv, -0.999999f), 0.999999f);
    float sd = f3dot(f3cross(v1, v2), v0);
    float sgn = (sd > 0.f) ? 1.f : ((sd < 0.f) ? -1.f : 0.f);
    float d = sgn * acosf(cosv);
    return isfinite(d) ? d : 0.f;
}

__global__ void dihed_kernel(const float* __restrict__ pos) {
    int idx = blockIdx.x * 256 + threadIdx.x;        // NB*L*L threads exactly
    int n = idx >> 16, i = (idx >> 8) & 255, j = idx & 255;
    const float* pi = pos + (size_t)(n * LRES + i) * NATOM * 3;
    const float* pj = pos + (size_t)(n * LRES + j) * NATOM * 3;
    float3 Ni  = make_float3(pi[0], pi[1], pi[2]);
    float3 CAi = make_float3(pi[3], pi[4], pi[5]);
    float3 Ci  = make_float3(pi[6], pi[7], pi[8]);
    float3 Nj  = make_float3(pj[0], pj[1], pj[2]);
    float3 CAj = make_float3(pj[3], pj[4], pj[5]);
    float3 Cj  = make_float3(pj[6], pj[7], pj[8]);
    float phi = dihedral_f(Ci, Nj, CAj, Cj);
    float psi = dihedral_f(Ni, CAi, Ci, Nj);
    g_dihed[(size_t)idx * 2 + 0] = phi;
    g_dihed[(size_t)idx * 2 + 1] = psi;
}

// ---------------- fused main kernel ----------------
// Tile: 128 pairs (8 i x 16 j) x 128 feat. 16 warps: g=warp&7 -> 16-feature
// slice [g*16, g*16+16); h=warp>>3 -> pair half. Each thread owns pairs
// p0=h*64+lane, p1=p0+32 with 2x8 packed-f32x2 accumulators. A is k-major.
struct __align__(16) Smem {
    float bufG[MPAIR * TPAIR];  // 100.4KB: stage1 act G; reused later
    float bufB[FEAT * TPAIR];   // 64KB ping-pong
    float sW[32 * FEAT];        // 16KB weight chunk
    float wdh[26 * FEAT];       // 13KB dihedral weight rows of out_w1
    float dcode[TPAIR * 26];    // 13.3KB
    float posI[8 * NATOM * 3];
    float posJ[16 * NATOM * 3];
    float maskI[8 * NATOM];
    float maskJ[16 * NATOM];
    float b1[FEAT]; float b2[FEAT]; float b3[FEAT]; float b4[FEAT]; float b5[FEAT];
    float sc[TPAIR]; float mp[TPAIR];
    int aap[TPAIR]; int rel[TPAIR];
    int aaI[8]; int aaJ[16]; int resI[8]; int resJ[16]; int chI[8]; int chJ[16];
};

// accA/accB[p][fbase..fbase+16) += sum_k A[k][p] * W[k][f], weight chunks
// double-buffered through registers (prefetch next chunk during compute).
template<int K>
__device__ __forceinline__ void gemm_acc(const float* __restrict__ Wg,
                                         const float* __restrict__ sAct,
                                         float* __restrict__ sW,
                                         ull accA[8], ull accB[8],
                                         int tid, int p0, int p1, int fbase) {
    constexpr int NCH = (K + 31) / 32;
    float4 r0, r1;
    {   // prefetch chunk 0 (32x128 floats = 1024 float4, 512 threads -> 2 each)
        const float4* src = (const float4*)Wg;
        constexpr int lim = (K < 32 ? K : 32) * 32;
        if (tid < lim)       r0 = src[tid];
        if (tid + 512 < lim) r1 = src[tid + 512];
    }
    #pragma unroll 1
    for (int c = 0; c < NCH; c++) {
        const int k0 = c * 32;
        const int rows = (K - k0 < 32) ? (K - k0) : 32;
        __syncthreads();
        {   // commit prefetched chunk to smem
            float4* dst = (float4*)sW;
            const int lim = rows * 32;
            if (tid < lim)       dst[tid] = r0;
            if (tid + 512 < lim) dst[tid + 512] = r1;
        }
        if (c + 1 < NCH) {  // prefetch next chunk
            const float4* src = (const float4*)(Wg + (k0 + 32) * FEAT);
            const int lim = ((K - k0 - 32 < 32) ? (K - k0 - 32) : 32) * 32;
            if (tid < lim)       r0 = src[tid];
            if (tid + 512 < lim) r1 = src[tid + 512];
        }
        __syncthreads();
        if (rows == 32) {
            #pragma unroll 8
            for (int kk = 0; kk < 32; kk++) {
                const float* arow = sAct + (k0 + kk) * TPAIR;
                float a0 = arow[p0], a1 = arow[p1];
                ull av0 = pack2(a0, a0), av1 = pack2(a1, a1);
                const ulonglong2* wr = (const ulonglong2*)(sW + kk * FEAT + fbase);
                #pragma unroll
                for (int q = 0; q < 4; q++) {
                    ulonglong2 w2 = wr[q];
                    fma2(accA[2 * q],     av0, w2.x);
                    fma2(accA[2 * q + 1], av0, w2.y);
                    fma2(accB[2 * q],     av1, w2.x);
                    fma2(accB[2 * q + 1], av1, w2.y);
                }
            }
        } else {
            for (int kk = 0; kk < rows; kk++) {
                const float* arow = sAct + (k0 + kk) * TPAIR;
                float a0 = arow[p0], a1 = arow[p1];
                ull av0 = pack2(a0, a0), av1 = pack2(a1, a1);
                const ulonglong2* wr = (const ulonglong2*)(sW + kk * FEAT + fbase);
                #pragma unroll
                for (int q = 0; q < 4; q++) {
                    ulonglong2 w2 = wr[q];
                    fma2(accA[2 * q],     av0, w2.x);
                    fma2(accA[2 * q + 1], av0, w2.y);
                    fma2(accB[2 * q],     av1, w2.x);
                    fma2(accB[2 * q + 1], av1, w2.y);
                }
            }
        }
    }
}

// relu(acc + bias) -> dst in k-major layout dst[f][p]
__device__ __forceinline__ void epilogue(ull accA[8], ull accB[8],
                                         const float* __restrict__ bias,
                                         float* __restrict__ dst, int p0, int p1, int fbase) {
    #pragma unroll
    for (int t = 0; t < 8; t++) {
        float2 va = unpack2(accA[t]);
        float2 vb = unpack2(accB[t]);
        int f = fbase + 2 * t;
        float bx = bias[f], by = bias[f + 1];
        dst[f * TPAIR + p0]       = fmaxf(va.x + bx, 0.f);
        dst[(f + 1) * TPAIR + p0] = fmaxf(va.y + by, 0.f);
        dst[f * TPAIR + p1]       = fmaxf(vb.x + bx, 0.f);
        dst[(f + 1) * TPAIR + p1] = fmaxf(vb.y + by, 0.f);
    }
}

__global__ void __launch_bounds__(NTHREADS, 1)
fused_kernel(const int* __restrict__ aa, const int* __restrict__ res_nb,
             const int* __restrict__ chain_nb, const float* __restrict__ pos,
             const float* __restrict__ mask,
             const float* __restrict__ dw1, const float* __restrict__ db1,
             const float* __restrict__ dw2, const float* __restrict__ db2,
             const float* __restrict__ ow1, const float* __restrict__ ob1,
             const float* __restrict__ ow2, const float* __restrict__ ob2,
             const float* __restrict__ ow3, const float* __restrict__ ob3,
             float* __restrict__ outp) {
    extern __shared__ char smem_raw[];
    Smem& s = *reinterpret_cast<Smem*>(smem_raw);
    const int tid = threadIdx.x;
    const int warp = tid >> 5, lane = tid & 31;
    const int fbase = (warp & 7) * 16;
    const int p0 = (warp >> 3) * 64 + lane;
    const int p1 = p0 + 32;
    const int bid = blockIdx.x;
    const int n  = bid >> 9;                 // 32*16 tiles per batch
    const int i0 = ((bid >> 4) & 31) * 8;
    const int j0 = (bid & 15) * 16;

    // ---- phase 0: cooperative loads ----
    {
        const float* pbI = pos + (size_t)(n * LRES + i0) * NATOM * 3;
        const float* pbJ = pos + (size_t)(n * LRES + j0) * NATOM * 3;
        if (tid < 8 * NATOM * 3)  s.posI[tid] = pbI[tid];
        // posJ has 16*14*3 = 672 floats > 512 threads: two strided slots
        if (tid < 16 * NATOM * 3)       s.posJ[tid] = pbJ[tid];
        if (tid + 512 < 16 * NATOM * 3) s.posJ[tid + 512] = pbJ[tid + 512];
        const float* mbI = mask + (size_t)(n * LRES + i0) * NATOM;
        const float* mbJ = mask + (size_t)(n * LRES + j0) * NATOM;
        if (tid < 8 * NATOM)  s.maskI[tid] = mbI[tid];
        if (tid < 16 * NATOM) s.maskJ[tid] = mbJ[tid];
        if (tid >= 256 && tid < 264) {
            int t = tid - 256;
            s.aaI[t]  = aa[n * LRES + i0 + t];
            s.resI[t] = res_nb[n * LRES + i0 + t];
            s.chI[t]  = chain_nb[n * LRES + i0 + t];
        }
        if (tid >= 288 && tid < 304) {
            int t = tid - 288;
            s.aaJ[t]  = aa[n * LRES + j0 + t];
            s.resJ[t] = res_nb[n * LRES + j0 + t];
            s.chJ[t]  = chain_nb[n * LRES + j0 + t];
        }
        if (tid >= 320 && tid < 448) {
            int t = tid - 320;
            s.b1[t] = db1[t]; s.b2[t] = db2[t]; s.b3[t] = ob1[t];
            s.b4[t] = ob2[t]; s.b5[t] = ob3[t];
        }
        for (int idx = tid; idx < 26 * FEAT; idx += NTHREADS) s.wdh[idx] = ow1[384 * FEAT + idx];
    }
    __syncthreads();

    // ---- phase 0b: per-pair meta + dihedral angular codes ----
    if (tid < TPAIR) {
        int ii = tid >> 4, jj = tid & 15;
        s.aap[tid] = s.aaI[ii] * MAXAA + s.aaJ[jj];
        int r = s.resI[ii] - s.resJ[jj];
        s.rel[tid] = min(max(r, -32), 32) + 32;
        s.sc[tid] = (s.chI[ii] == s.chJ[jj]) ? 1.f : 0.f;
        s.mp[tid] = s.maskI[ii * NATOM + 1] * s.maskJ[jj * NATOM + 1];   // CA masks
        const float* dh = &g_dihed[((size_t)(n * LRES + i0 + ii) * LRES + (j0 + jj)) * 2];
        float phi = dh[0], psi = dh[1];
        float* c = &s.dcode[tid * 26];
        const float FRQ[6] = {1.f, 2.f, 3.f, 1.f, 0.5f, 1.f / 3.f};
        c[0] = phi; c[13] = psi;
        #pragma unroll
        for (int t = 0; t < 6; t++) {
            float sv, cv;
            sincosf(phi * FRQ[t], &sv, &cv); c[1 + t]  = sv; c[7 + t]  = cv;
            sincosf(psi * FRQ[t], &sv, &cv); c[14 + t] = sv; c[20 + t] = cv;
        }
    }
    __syncthreads();

    // ---- phase 1: masked gaussian distance features, k-major G[m][p] ----
    for (int idx = tid; idx < TPAIR * MPAIR; idx += NTHREADS) {
        int m = idx >> 7;
        int pp = idx & (TPAIR - 1);
        int a = m / NATOM;
        int b = m - a * NATOM;
        int ii = pp >> 4, jj = pp & 15;
        float dx = s.posI[ii * 42 + a * 3 + 0] - s.posJ[jj * 42 + b * 3 + 0];
        float dy = s.posI[ii * 42 + a * 3 + 1] - s.posJ[jj * 42 + b * 3 + 1];
        float dz = s.posI[ii * 42 + a * 3 + 2] - s.posJ[jj * 42 + b * 3 + 2];
        float ss = dx * dx + dy * dy + dz * dz;        // (10*d)^2
        float cc = g_softc[s.aap[pp] * MPAIR + m];
        float g = __expf(-cc * ss * 0.01f) * (s.maskI[ii * NATOM + a] * s.maskJ[jj * NATOM + b]);
        s.bufG[idx] = g;
    }
    // gemm's leading __syncthreads covers bufG visibility

    ull accA[8], accB[8];

    // ---- stage 1: h1 = relu(G @ dist_w1 + b1) -> bufB ----
    #pragma unroll
    for (int q = 0; q < 8; q++) { accA[q] = 0ull; accB[q] = 0ull; }
    gemm_acc<MPAIR>(dw1, s.bufG, s.sW, accA, accB, tid, p0, p1, fbase);
    epilogue(accA, accB, s.b1, s.bufB, p0, p1, fbase);

    // ---- stage 2: fd = relu(h1 @ dist_w2 + b2) -> bufG ----
    #pragma unroll
    for (int q = 0; q < 8; q++) { accA[q] = 0ull; accB[q] = 0ull; }
    gemm_acc<FEAT>(dw2, s.bufB, s.sW, accA, accB, tid, p0, p1, fbase);
    epilogue(accA, accB, s.b2, s.bufG, p0, p1, fbase);

    // ---- stage 3: h = relu(preA + sc*preR + dihed@Wdh + fd@Wdist + ob1) -> bufB ----
    {
        int ap0 = s.aap[p0], rl0 = s.rel[p0];
        int ap1 = s.aap[p1], rl1 = s.rel[p1];
        float sc0 = s.sc[p0], sc1 = s.sc[p1];
        const float4* A0 = (const float4*)&g_preA[ap0 * FEAT + fbase];
        const float4* R0 = (const float4*)&g_preR[rl0 * FEAT + fbase];
        const float4* A1 = (const float4*)&g_preA[ap1 * FEAT + fbase];
        const float4* R1 = (const float4*)&g_preR[rl1 * FEAT + fbase];
        #pragma unroll
        for (int q = 0; q < 4; q++) {
            float4 a4 = A0[q], r4 = R0[q];
            accA[2 * q]     = pack2(a4.x + sc0 * r4.x, a4.y + sc0 * r4.y);
            accA[2 * q + 1] = pack2(a4.z + sc0 * r4.z, a4.w + sc0 * r4.w);
            float4 b4v = A1[q], q4 = R1[q];
            accB[2 * q]     = pack2(b4v.x + sc1 * q4.x, b4v.y + sc1 * q4.y);
            accB[2 * q + 1] = pack2(b4v.z + sc1 * q4.z, b4v.w + sc1 * q4.w);
        }
        #pragma unroll
        for (int t = 0; t < 26; t++) {
            float d0 = s.dcode[p0 * 26 + t];
            float d1 = s.dcode[p1 * 26 + t];
            ull av0 = pack2(d0, d0), av1 = pack2(d1, d1);
            const ulonglong2* wr = (const ulonglong2*)(s.wdh + t * FEAT + fbase);
            #pragma unroll
            for (int q = 0; q < 4; q++) {
                ulonglong2 w2 = wr[q];
                fma2(accA[2 * q],     av0, w2.x);
                fma2(accA[2 * q + 1], av0, w2.y);
                fma2(accB[2 * q],     av1, w2.x);
                fma2(accB[2 * q + 1], av1, w2.y);
            }
        }
    }
    gemm_acc<FEAT>(ow1 + 256 * FEAT, s.bufG, s.sW, accA, accB, tid, p0, p1, fbase);
    epilogue(accA, accB, s.b3, s.bufB, p0, p1, fbase);

    // ---- stage 4: h = relu(h @ out_w2 + ob2) -> bufG ----
    #pragma unroll
    for (int q = 0; q < 8; q++) { accA[q] = 0ull; accB[q] = 0ull; }
    gemm_acc<FEAT>(ow2, s.bufB, s.sW, accA, accB, tid, p0, p1, fbase);
    epilogue(accA, accB, s.b4, s.bufG, p0, p1, fbase);

    // ---- stage 5: out = (h @ out_w3 + ob3) * mask_pair -> global ----
    #pragma unroll
    for (int q = 0; q < 8; q++) { accA[q] = 0ull; accB[q] = 0ull; }
    gemm_acc<FEAT>(ow3, s.bufG, s.sW, accA, accB, tid, p0, p1, fbase);
    #pragma unroll
    for (int half = 0; half < 2; half++) {
        ull* acc = half ? accB : accA;
        int p = half ? p1 : p0;
        int ii = p >> 4, jj = p & 15;
        float mpv = s.mp[p];
        float* orow = outp + ((((size_t)n * LRES + (i0 + ii)) * LRES + (j0 + jj)) * FEAT + fbase);
        #pragma unroll
        for (int q = 0; q < 4; q++) {
            float2 v0 = unpack2(acc[2 * q]);
            float2 v1 = unpack2(acc[2 * q + 1]);
            int f = fbase + 4 * q;
            float4 o = make_float4((v0.x + s.b5[f])     * mpv,
                                   (v0.y + s.b5[f + 1]) * mpv,
                                   (v1.x + s.b5[f + 2]) * mpv,
                                   (v1.y + s.b5[f + 3]) * mpv);
            *(float4*)&orow[4 * q] = o;
        }
    }
}

// ---------------- launch ----------------
extern "C" void kernel_launch(void* const* d_in, const int* in_sizes, int n_in,
                              void* d_out, int out_size) {
    const int*   aa        = (const int*)  d_in[0];
    const int*   res_nb    = (const int*)  d_in[1];
    const int*   chain_nb  = (const int*)  d_in[2];
    const float* pos       = (const float*)d_in[3];
    const float* mask      = (const float*)d_in[4];
    const float* aap_embed = (const float*)d_in[5];
    const float* rel_embed = (const float*)d_in[6];
    const float* distcoef  = (const float*)d_in[7];
    const float* dw1 = (const float*)d_in[8];
    const float* db1 = (const float*)d_in[9];
    const float* dw2 = (const float*)d_in[10];
    const float* db2 = (const float*)d_in[11];
    const float* ow1 = (const float*)d_in[12];
    const float* ob1 = (const float*)d_in[13];
    const float* ow2 = (const float*)d_in[14];
    const float* ob2 = (const float*)d_in[15];
    const float* ow3 = (const float*)d_in[16];
    const float* ob3 = (const float*)d_in[17];
    float* outp = (float*)d_out;

    cudaFuncSetAttribute(fused_kernel, cudaFuncAttributeMaxDynamicSharedMemorySize,
                         (int)sizeof(Smem));

    softc_kernel<<<(NAPAIR * MPAIR + 255) / 256, 256>>>(distcoef);
    pretab_kernel<<<NAPAIR + NREL, 128>>>(aap_embed, rel_embed, ow1);
    dihed_kernel<<<(NBATCH * LRES * LRES) / 256, 256>>>(pos);
    fused_kernel<<<NBATCH * 32 * 16, NTHREADS, sizeof(Smem)>>>(
        aa, res_nb, chain_nb, pos, mask,
        dw1, db1, dw2, db2, ow1, ob1, ow2, ob2, ow3, ob3, outp);
}